// round 3
// baseline (speedup 1.0000x reference)
#include <cuda_runtime.h>
#include <cstdint>

#define NB 4
#define LSEQ 16384
#define CCH 64
#define CM 16
#define NH 4
#define HB 128
#define KCH 128
#define JTOT (NH*LSEQ)
#define NKEY 640
#define TILE 512
#define NTILE (JTOT/TILE)
#define TL 64

typedef unsigned long long ull;

// ---------------- device scratch ----------------
__device__ __align__(16) float g_xembed[NB][LSEQ][CM];
__device__ __align__(16) float g_yembed[NB][LSEQ][CCH];
__device__ float g_xnorm[NB][LSEQ];
__device__ float g_invn[NB][LSEQ];
__device__ int   g_codes[NB][JTOT];
__device__ int   g_perm[NB][JTOT];
__device__ int   g_tileHist[NB][NTILE][NKEY];   // zero-initialized at load; re-zeroed by k_combine
__device__ int   g_keyBase[NB][NKEY];
__device__ __align__(16) float g_ret[NB][JTOT][CCH];
__device__ float g_bs[NB][JTOT];

// ---------------- helpers ----------------
__device__ __forceinline__ ull pk2(float a, float b){
    ull u; asm("mov.b64 %0,{%1,%2};" : "=l"(u) : "f"(a), "f"(b)); return u;
}
__device__ __forceinline__ void upk2(ull u, float& a, float& b){
    asm("mov.b64 {%0,%1},%2;" : "=f"(a), "=f"(b) : "l"(u));
}
__device__ __forceinline__ ull f2fma(ull a, ull b, ull c){
    ull d; asm("fma.rn.f32x2 %0,%1,%2,%3;" : "=l"(d) : "l"(a), "l"(b), "l"(c)); return d;
}
__device__ __forceinline__ float ex2a(float t){
    float r; asm("ex2.approx.f32 %0,%1;" : "=f"(r) : "f"(t)); return r;
}
__device__ __forceinline__ float lg2a(float t){
    float r; asm("lg2.approx.f32 %0,%1;" : "=f"(r) : "f"(t)); return r;
}
#define LOG2E 1.4426950408889634f
#define LN2   0.6931471805599453f

// ---------------- K0: fused embed + hash + hist ----------------
// dynamic smem layout (floats):
//   sx   [TL+2][64]      4224
//   swm  [192][16]       3072
//   swa  [64][64]        4096
//   swb  [64]              64
//   sxe  [TL][17]        1088
//   sR   [512][16]       8192   ([h*128+i][f])
#define OFF_SX   0
#define OFF_SWM  4224
#define OFF_SWA  (4224+3072)
#define OFF_SWB  (4224+3072+4096)
#define OFF_SXE  (4224+3072+4096+64)
#define OFF_SR   (4224+3072+4096+64+1088)
#define SMEM_EHH ((OFF_SR+8192)*4)

__global__ void k_ehh(const float* __restrict__ x, const float* __restrict__ wm,
                      const float* __restrict__ wa, const float* __restrict__ wb,
                      const float* __restrict__ rot){
    extern __shared__ float sm[];
    float (*sx)[64]  = (float(*)[64])(sm + OFF_SX);
    float (*swm)[16] = (float(*)[16])(sm + OFF_SWM);
    float (*swa)[64] = (float(*)[64])(sm + OFF_SWA);
    float *swb       = sm + OFF_SWB;
    float (*sxe)[17] = (float(*)[17])(sm + OFF_SXE);
    float (*sR)[16]  = (float(*)[16])(sm + OFF_SR);

    int b = blockIdx.x;
    int n = b / (LSEQ/TL);
    int l0 = (b % (LSEQ/TL)) * TL;
    int tid = threadIdx.x;

    for (int idx = tid; idx < (TL+2)*64; idx += 256){
        int r = idx >> 6, c = idx & 63;
        int l = l0 + r - 1;
        sx[r][c] = (l >= 0 && l < LSEQ) ? x[((size_t)n*LSEQ + l)*64 + c] : 0.f;
    }
    for (int idx = tid; idx < 3072; idx += 256){
        int f = idx / 192, rem = idx % 192;
        swm[rem][f] = wm[idx];
    }
    for (int idx = tid; idx < 4096; idx += 256){
        int o = idx >> 6, c = idx & 63;
        swa[c][o] = wa[idx];
    }
    if (tid < 64) swb[tid] = wb[tid];
    // rotations: rot[f*512 + h*128 + i] -> sR[h*128+i][f]
    for (int idx = tid; idx < 8192; idx += 256){
        int f = idx >> 9, hi = idx & 511;
        sR[hi][f] = rot[idx];
    }
    __syncthreads();

    // x_embed (conv3, 64 -> 16)
    for (int idx = tid; idx < TL*16; idx += 256){
        int lr = idx >> 4, f = idx & 15;
        float acc = 0.f;
        #pragma unroll 8
        for (int c = 0; c < 64; c++){
            acc = fmaf(sx[lr  ][c], swm[c*3+0][f], acc);
            acc = fmaf(sx[lr+1][c], swm[c*3+1][f], acc);
            acc = fmaf(sx[lr+2][c], swm[c*3+2][f], acc);
        }
        g_xembed[n][l0+lr][f] = acc;
        sxe[lr][f] = acc;
    }
    // y_embed (1x1 conv + bias)
    for (int idx = tid; idx < TL*64; idx += 256){
        int lr = idx >> 6, o = idx & 63;
        float acc = swb[o];
        #pragma unroll 8
        for (int c = 0; c < 64; c++)
            acc = fmaf(sx[lr+1][c], swa[c][o], acc);
        g_yembed[n][l0+lr][o] = acc;
    }
    __syncthreads();

    // hash: thread = (h, ll)
    int h = tid >> 6, ll = tid & 63;
    int l = l0 + ll;
    float q[16];
    #pragma unroll
    for (int f = 0; f < 16; f++) q[f] = sxe[ll][f];

    if (h == 0){
        float nn = 0.f;
        #pragma unroll
        for (int f = 0; f < 16; f++) nn = fmaf(q[f], q[f], nn);
        nn = sqrtf(nn);
        g_xnorm[n][l] = nn;
        g_invn[n][l]  = 1.f / fmaxf(nn, 5e-5f);
    }
    float m1 = -1e30f, m2 = 1e30f; int i1 = 0, i2 = 0;
    const float (*Rh)[16] = &sR[h*128];
    for (int i = 0; i < 128; i++){
        float v = 0.f;
        #pragma unroll
        for (int f = 0; f < 16; f++) v = fmaf(q[f], Rh[i][f], v);
        if (v > m1){ m1 = v; i1 = i; }
        if (v < m2){ m2 = v; i2 = i; }
    }
    int code = ((m1 >= -m2) ? i1 : (HB + i2)) + h*HB;
    int j = h*LSEQ + l;
    g_codes[n][j] = code;
    atomicAdd(&g_tileHist[n][j >> 9][code], 1);
}

// ---------------- K1: tile-prefix + key base (parallel scan) ----------------
__global__ void k_scan(){
    __shared__ int stot[NKEY];
    __shared__ int sc[1024];
    int n = blockIdx.x; int k = threadIdx.x;
    if (k < NKEY){
        int run = 0;
        #pragma unroll 4
        for (int tl = 0; tl < NTILE; tl++){
            int v = g_tileHist[n][tl][k];
            g_tileHist[n][tl][k] = run;
            run += v;
        }
        stot[k] = run;
    }
    __syncthreads();
    int v0 = (k < NKEY) ? stot[k] : 0;
    sc[k] = v0;
    __syncthreads();
    #pragma unroll
    for (int off = 1; off < 1024; off <<= 1){
        int add = (k >= off) ? sc[k-off] : 0;
        __syncthreads();
        sc[k] += add;
        __syncthreads();
    }
    if (k < NKEY) g_keyBase[n][k] = sc[k] - v0;   // exclusive prefix
}

// ---------------- K2: stable scatter ----------------
__global__ void k_scatter(){
    __shared__ int skey[TILE];
    int b = blockIdx.x; int n = b >> 7, tl = b & 127;
    int t = threadIdx.x;
    int key = g_codes[n][tl*TILE + t];
    skey[t] = key;
    __syncthreads();
    int r = 0;
    for (int u = 0; u < TILE; u++){
        int ku = skey[u];
        if (u < t && ku == key) r++;
    }
    int pos = g_keyBase[n][key] + g_tileHist[n][tl][key] + r;
    g_perm[n][pos] = tl*TILE + t;
}

// ---------------- K3: chunked attention ----------------
__global__ void __launch_bounds__(128) k_attn(){
    __shared__ __align__(16) float skey[128][20];
    __shared__ __align__(16) float sval[128][68];
    int cid = blockIdx.x;
    int n = cid >> 9, rem = cid & 511;
    int g = rem >> 7, k = rem & 127;
    int i = threadIdx.x;

    int p = (g << 14) + (k << 7) + i;
    int j = g_perm[n][p];
    int l = j & (LSEQ - 1);

    float q[16];
    const float4* qp = (const float4*)&g_xembed[n][l][0];
    #pragma unroll
    for (int t = 0; t < 4; t++){
        float4 v = qp[t];
        q[4*t] = v.x; q[4*t+1] = v.y; q[4*t+2] = v.z; q[4*t+3] = v.w;
    }
    ull q2[8];
    #pragma unroll
    for (int u = 0; u < 8; u++) q2[u] = pk2(q[2*u]*LOG2E, q[2*u+1]*LOG2E);

    float m = g_xnorm[n][l];
    float mb = -m * LOG2E;           // exp(d - m) = ex2(d*log2e - m*log2e)
    float s = 0.f;
    ull acc[32];
    #pragma unroll
    for (int u = 0; u < 32; u++) acc[u] = 0ull;

    for (int pass = 0; pass < 3; pass++){
        int kc = (pass == 0) ? k : (pass == 1) ? ((k + 127) & 127) : ((k + 1) & 127);
        __syncthreads();
        {
            int p2 = (g << 14) + (kc << 7) + i;
            int j2 = g_perm[n][p2];
            int l2 = j2 & (LSEQ - 1);
            float inv = g_invn[n][l2];
            const float4* kp = (const float4*)&g_xembed[n][l2][0];
            #pragma unroll
            for (int t = 0; t < 4; t++){
                float4 v = kp[t];
                v.x *= inv; v.y *= inv; v.z *= inv; v.w *= inv;
                *(float4*)&skey[i][4*t] = v;
            }
            const float4* vp = (const float4*)&g_yembed[n][l2][0];
            #pragma unroll
            for (int t = 0; t < 16; t++)
                *(float4*)&sval[i][4*t] = vp[t];
        }
        __syncthreads();

        #pragma unroll 2
        for (int jj = 0; jj < 128; jj++){
            const ulonglong2* kk = (const ulonglong2*)&skey[jj][0];
            ull d0 = 0ull, d1 = 0ull;
            #pragma unroll
            for (int t = 0; t < 4; t++){
                ulonglong2 kv = kk[t];
                d0 = f2fma(q2[2*t],   kv.x, d0);
                d1 = f2fma(q2[2*t+1], kv.y, d1);
            }
            float ax, ay, bx, by; upk2(d0, ax, ay); upk2(d1, bx, by);
            float e = ex2a((ax + bx) + (ay + by) + mb);   // MUFU pipe
            s += e;
            ull ee = pk2(e, e);
            const ulonglong2* vv = (const ulonglong2*)&sval[jj][0];
            #pragma unroll
            for (int t = 0; t < 16; t++){
                ulonglong2 v2 = vv[t];
                acc[2*t]   = f2fma(ee, v2.x, acc[2*t]);
                acc[2*t+1] = f2fma(ee, v2.y, acc[2*t+1]);
            }
        }
    }
    float rs = 1.f / s;
    float4* outp = (float4*)&g_ret[n][j][0];
    #pragma unroll
    for (int t = 0; t < 16; t++){
        float a, bb, c, d;
        upk2(acc[2*t],   a, bb);
        upk2(acc[2*t+1], c, d);
        float4 o; o.x = a*rs; o.y = bb*rs; o.z = c*rs; o.w = d*rs;
        outp[t] = o;
    }
    g_bs[n][j] = m + lg2a(s) * LN2;
}

// ---------------- K4: softmax-over-hash combine + residual + hist re-zero ----------------
__global__ void k_combine(const float* __restrict__ x, float* __restrict__ out){
    int gt = blockIdx.x * 256 + threadIdx.x;
    int n = gt >> 14, l = gt & (LSEQ - 1);
    float b0 = g_bs[n][l];
    float b1 = g_bs[n][LSEQ + l];
    float b2 = g_bs[n][2*LSEQ + l];
    float b3 = g_bs[n][3*LSEQ + l];
    float mx = fmaxf(fmaxf(b0, b1), fmaxf(b2, b3));
    float e0 = ex2a((b0 - mx)*LOG2E), e1 = ex2a((b1 - mx)*LOG2E);
    float e2 = ex2a((b2 - mx)*LOG2E), e3 = ex2a((b3 - mx)*LOG2E);
    float inv = 1.f / (e0 + e1 + e2 + e3);
    float p0 = e0*inv, p1 = e1*inv, p2 = e2*inv, p3 = e3*inv;

    const float4* x4 = (const float4*)&x[((size_t)n*LSEQ + l)*64];
    const float4* r0 = (const float4*)&g_ret[n][l][0];
    const float4* r1 = (const float4*)&g_ret[n][LSEQ + l][0];
    const float4* r2 = (const float4*)&g_ret[n][2*LSEQ + l][0];
    const float4* r3 = (const float4*)&g_ret[n][3*LSEQ + l][0];
    float4* o4 = (float4*)&out[((size_t)n*LSEQ + l)*64];
    #pragma unroll
    for (int t = 0; t < 16; t++){
        float4 a = x4[t];
        float4 v0 = r0[t], v1 = r1[t], v2 = r2[t], v3 = r3[t];
        float4 o;
        o.x = a.x + p0*v0.x + p1*v1.x + p2*v2.x + p3*v3.x;
        o.y = a.y + p0*v0.y + p1*v1.y + p2*v2.y + p3*v3.y;
        o.z = a.z + p0*v0.z + p1*v1.z + p2*v2.z + p3*v3.z;
        o.w = a.w + p0*v0.w + p1*v1.w + p2*v2.w + p3*v3.w;
        o4[t] = o;
    }
    // re-zero histogram for the next graph replay (deterministic: runs every call)
    int* hist = &g_tileHist[0][0][0];
    const int tot = NB*NTILE*NKEY;
    for (int idx = gt; idx < tot; idx += NB*LSEQ) hist[idx] = 0;
}

// ---------------- launch ----------------
extern "C" void kernel_launch(void* const* d_in, const int* in_sizes, int n_in,
                              void* d_out, int out_size){
    const float* x  = (const float*)d_in[0];
    const float* wm = (const float*)d_in[1];
    const float* wa = (const float*)d_in[2];
    const float* wb = (const float*)d_in[3];
    const float* rt = (const float*)d_in[4];
    float* out = (float*)d_out;

    static bool attr_done = false;
    if (!attr_done){
        cudaFuncSetAttribute(k_ehh, cudaFuncAttributeMaxDynamicSharedMemorySize, SMEM_EHH);
        attr_done = true;
    }

    k_ehh    <<<NB*(LSEQ/TL), 256, SMEM_EHH>>>(x, wm, wa, wb, rt);
    k_scan   <<<NB, 1024>>>();
    k_scatter<<<NB*NTILE, TILE>>>();
    k_attn   <<<NB*NH*KCH, 128>>>();
    k_combine<<<(NB*LSEQ)/256, 256>>>(x, out);
}

// round 4
// speedup vs baseline: 2.0421x; 2.0421x over previous
#include <cuda_runtime.h>
#include <cstdint>

#define NB 4
#define LSEQ 16384
#define CCH 64
#define CM 16
#define NH 4
#define HB 128
#define KCH 128
#define JTOT (NH*LSEQ)
#define NKEY 640
#define TILE 512
#define NTILE (JTOT/TILE)
#define TL 64

typedef unsigned long long ull;
typedef unsigned int uint32;

// ---------------- device scratch ----------------
__device__ __align__(16) float g_xembed[NB][LSEQ][CM];
__device__ __align__(16) float g_yembed[NB][LSEQ][CCH];
__device__ float g_xnorm[NB][LSEQ];
__device__ float g_invn[NB][LSEQ];
__device__ int   g_codes[NB][JTOT];
__device__ int   g_perm[NB][JTOT];
__device__ int   g_tileHist[NB][NTILE][NKEY];   // zeroed at load; re-zeroed by k_combine
__device__ int   g_keyBase[NB][NKEY];
__device__ __align__(16) unsigned short g_ret[NB][JTOT][CCH];   // bf16
__device__ float g_bs[NB][JTOT];

// ---------------- helpers ----------------
__device__ __forceinline__ float ex2a(float t){
    float r; asm("ex2.approx.f32 %0,%1;" : "=f"(r) : "f"(t)); return r;
}
__device__ __forceinline__ float lg2a(float t){
    float r; asm("lg2.approx.f32 %0,%1;" : "=f"(r) : "f"(t)); return r;
}
// pack two f32 -> bf16x2 {lo, hi}  (first PTX source goes to HIGH half)
__device__ __forceinline__ uint32 pkbf(float lo, float hi){
    uint32 r; asm("cvt.rn.bf16x2.f32 %0, %1, %2;" : "=r"(r) : "f"(hi), "f"(lo)); return r;
}
__device__ __forceinline__ float blo(uint32 u){ return __uint_as_float(u << 16); }
__device__ __forceinline__ float bhi(uint32 u){ return __uint_as_float(u & 0xffff0000u); }

__device__ __forceinline__ void mma16816(float* d, const uint32* a, uint32 b0, uint32 b1){
    asm volatile("mma.sync.aligned.m16n8k16.row.col.f32.bf16.bf16.f32 "
        "{%0,%1,%2,%3},{%4,%5,%6,%7},{%8,%9},{%0,%1,%2,%3};"
        : "+f"(d[0]), "+f"(d[1]), "+f"(d[2]), "+f"(d[3])
        : "r"(a[0]), "r"(a[1]), "r"(a[2]), "r"(a[3]), "r"(b0), "r"(b1));
}

#define LOG2E 1.4426950408889634f
#define LN2   0.6931471805599453f

// ---------------- K0: fused embed + hash + hist ----------------
#define OFF_SX   0
#define OFF_SWM  4224
#define OFF_SWA  (4224+3072)
#define OFF_SWB  (4224+3072+4096)
#define OFF_SXE  (4224+3072+4096+64)
#define OFF_SR   (4224+3072+4096+64+1088)
#define SMEM_EHH ((OFF_SR+8192)*4)

__global__ void k_ehh(const float* __restrict__ x, const float* __restrict__ wm,
                      const float* __restrict__ wa, const float* __restrict__ wb,
                      const float* __restrict__ rot){
    extern __shared__ float sm[];
    float (*sx)[64]  = (float(*)[64])(sm + OFF_SX);
    float (*swm)[16] = (float(*)[16])(sm + OFF_SWM);
    float (*swa)[64] = (float(*)[64])(sm + OFF_SWA);
    float *swb       = sm + OFF_SWB;
    float (*sxe)[17] = (float(*)[17])(sm + OFF_SXE);
    float (*sR)[16]  = (float(*)[16])(sm + OFF_SR);

    int b = blockIdx.x;
    int n = b / (LSEQ/TL);
    int l0 = (b % (LSEQ/TL)) * TL;
    int tid = threadIdx.x;

    for (int idx = tid; idx < (TL+2)*64; idx += 256){
        int r = idx >> 6, c = idx & 63;
        int l = l0 + r - 1;
        sx[r][c] = (l >= 0 && l < LSEQ) ? x[((size_t)n*LSEQ + l)*64 + c] : 0.f;
    }
    for (int idx = tid; idx < 3072; idx += 256){
        int f = idx / 192, rem = idx % 192;
        swm[rem][f] = wm[idx];
    }
    for (int idx = tid; idx < 4096; idx += 256){
        int o = idx >> 6, c = idx & 63;
        swa[c][o] = wa[idx];
    }
    if (tid < 64) swb[tid] = wb[tid];
    for (int idx = tid; idx < 8192; idx += 256){
        int f = idx >> 9, hi = idx & 511;
        sR[hi][f] = rot[idx];
    }
    __syncthreads();

    for (int idx = tid; idx < TL*16; idx += 256){
        int lr = idx >> 4, f = idx & 15;
        float acc = 0.f;
        #pragma unroll 8
        for (int c = 0; c < 64; c++){
            acc = fmaf(sx[lr  ][c], swm[c*3+0][f], acc);
            acc = fmaf(sx[lr+1][c], swm[c*3+1][f], acc);
            acc = fmaf(sx[lr+2][c], swm[c*3+2][f], acc);
        }
        g_xembed[n][l0+lr][f] = acc;
        sxe[lr][f] = acc;
    }
    for (int idx = tid; idx < TL*64; idx += 256){
        int lr = idx >> 6, o = idx & 63;
        float acc = swb[o];
        #pragma unroll 8
        for (int c = 0; c < 64; c++)
            acc = fmaf(sx[lr+1][c], swa[c][o], acc);
        g_yembed[n][l0+lr][o] = acc;
    }
    __syncthreads();

    int h = tid >> 6, ll = tid & 63;
    int l = l0 + ll;
    float q[16];
    #pragma unroll
    for (int f = 0; f < 16; f++) q[f] = sxe[ll][f];

    if (h == 0){
        float nn = 0.f;
        #pragma unroll
        for (int f = 0; f < 16; f++) nn = fmaf(q[f], q[f], nn);
        nn = sqrtf(nn);
        g_xnorm[n][l] = nn;
        g_invn[n][l]  = 1.f / fmaxf(nn, 5e-5f);
    }
    float m1 = -1e30f, m2 = 1e30f; int i1 = 0, i2 = 0;
    const float (*Rh)[16] = &sR[h*128];
    for (int i = 0; i < 128; i++){
        float v = 0.f;
        #pragma unroll
        for (int f = 0; f < 16; f++) v = fmaf(q[f], Rh[i][f], v);
        if (v > m1){ m1 = v; i1 = i; }
        if (v < m2){ m2 = v; i2 = i; }
    }
    int code = ((m1 >= -m2) ? i1 : (HB + i2)) + h*HB;
    int j = h*LSEQ + l;
    g_codes[n][j] = code;
    atomicAdd(&g_tileHist[n][j >> 9][code], 1);
}

// ---------------- K1: tile-prefix + key base ----------------
__global__ void k_scan(){
    __shared__ int stot[NKEY];
    __shared__ int sc[1024];
    int n = blockIdx.x; int k = threadIdx.x;
    if (k < NKEY){
        int run = 0;
        #pragma unroll 4
        for (int tl = 0; tl < NTILE; tl++){
            int v = g_tileHist[n][tl][k];
            g_tileHist[n][tl][k] = run;
            run += v;
        }
        stot[k] = run;
    }
    __syncthreads();
    int v0 = (k < NKEY) ? stot[k] : 0;
    sc[k] = v0;
    __syncthreads();
    #pragma unroll
    for (int off = 1; off < 1024; off <<= 1){
        int add = (k >= off) ? sc[k-off] : 0;
        __syncthreads();
        sc[k] += add;
        __syncthreads();
    }
    if (k < NKEY) g_keyBase[n][k] = sc[k] - v0;
}

// ---------------- K2: stable scatter ----------------
__global__ void k_scatter(){
    __shared__ int skey[TILE];
    int b = blockIdx.x; int n = b >> 7, tl = b & 127;
    int t = threadIdx.x;
    int key = g_codes[n][tl*TILE + t];
    skey[t] = key;
    __syncthreads();
    int r = 0;
    for (int u = 0; u < TILE; u++){
        int ku = skey[u];
        if (u < t && ku == key) r++;
    }
    int pos = g_keyBase[n][key] + g_tileHist[n][tl][key] + r;
    g_perm[n][pos] = tl*TILE + t;
}

// ---------------- K3: chunked attention, bf16 tensor cores ----------------
// dynamic smem (uint32 words):
#define OQ   0          // sQ  [128][8]   bf16x2 words (row-major, word f = feats 2f,2f+1)
#define OK_  1024       // sK  [384][8]
#define OVT  4096       // sVT [64][204]  word kp = keys 2kp,2kp+1 (pitch 204 % 32 == 12)
#define OM2  17152      // float m*LOG2E per query row [128]
#define OJ_  17280      // j per query row [128]
#define OL_  17408      // l per key row [384]
#define SMEM_ATTN ((17408+384)*4)

__global__ void __launch_bounds__(128) k_attn(){
    extern __shared__ uint32 smw[];
    uint32* sQ  = smw + OQ;
    uint32* sK  = smw + OK_;
    uint32* sVT = smw + OVT;
    float*  sM2 = (float*)(smw + OM2);
    int*    sJ  = (int*)(smw + OJ_);
    int*    sL  = (int*)(smw + OL_);

    int cid = blockIdx.x;
    int n = cid >> 9, rem = cid & 511;
    int g = rem >> 7, k = rem & 127;
    int tid = threadIdx.x;
    int lane = tid & 31, w = tid >> 5;
    int g4 = lane >> 2, t4 = lane & 3;

    // ---- stage 1: gather Q (chunk k) and K (chunks k, k-1, k+1) ----
    #pragma unroll
    for (int s = 0; s < 3; s++){
        int kc = (s == 0) ? k : (s == 1) ? ((k + 127) & 127) : ((k + 1) & 127);
        int key = s*128 + tid;
        int p = (g << 14) + (kc << 7) + tid;
        int j = g_perm[n][p];
        int l = j & (LSEQ - 1);
        sL[key] = l;
        float inv = g_invn[n][l];
        const float4* xp = (const float4*)&g_xembed[n][l][0];
        float4 v0 = xp[0], v1 = xp[1], v2 = xp[2], v3 = xp[3];
        uint32* kr = &sK[key*8];
        kr[0] = pkbf(v0.x*inv, v0.y*inv); kr[1] = pkbf(v0.z*inv, v0.w*inv);
        kr[2] = pkbf(v1.x*inv, v1.y*inv); kr[3] = pkbf(v1.z*inv, v1.w*inv);
        kr[4] = pkbf(v2.x*inv, v2.y*inv); kr[5] = pkbf(v2.z*inv, v2.w*inv);
        kr[6] = pkbf(v3.x*inv, v3.y*inv); kr[7] = pkbf(v3.z*inv, v3.w*inv);
        if (s == 0){
            sJ[tid] = j;
            sM2[tid] = g_xnorm[n][l] * LOG2E;
            uint32* qr = &sQ[tid*8];
            qr[0] = pkbf(v0.x*LOG2E, v0.y*LOG2E); qr[1] = pkbf(v0.z*LOG2E, v0.w*LOG2E);
            qr[2] = pkbf(v1.x*LOG2E, v1.y*LOG2E); qr[3] = pkbf(v1.z*LOG2E, v1.w*LOG2E);
            qr[4] = pkbf(v2.x*LOG2E, v2.y*LOG2E); qr[5] = pkbf(v2.z*LOG2E, v2.w*LOG2E);
            qr[6] = pkbf(v3.x*LOG2E, v3.y*LOG2E); qr[7] = pkbf(v3.z*LOG2E, v3.w*LOG2E);
        }
    }
    __syncthreads();

    // ---- stage 2: V gather, transposed to sVT[ch][keypair] ----
    {
        int a = g4, b = t4;
        int ch0 = w*16 + a, ch1 = ch0 + 8;
        const float* yb = &g_yembed[n][0][0];
        #pragma unroll 4
        for (int kp = b; kp < 192; kp += 4){
            int l0 = sL[2*kp] << 6, l1 = sL[2*kp+1] << 6;
            float a0 = yb[l0 + ch0], a1 = yb[l1 + ch0];
            float b0 = yb[l0 + ch1], b1 = yb[l1 + ch1];
            sVT[ch0*204 + kp] = pkbf(a0, a1);
            sVT[ch1*204 + kp] = pkbf(b0, b1);
        }
    }
    __syncthreads();

    // ---- main loop ----
    int rbase = w*32;
    uint32 qf[2][4];
    float m2lo[2], m2hi[2];
    #pragma unroll
    for (int rt = 0; rt < 2; rt++){
        int row = rbase + rt*16 + g4;
        qf[rt][0] = sQ[row*8 + t4];
        qf[rt][1] = sQ[(row+8)*8 + t4];
        qf[rt][2] = sQ[row*8 + 4 + t4];
        qf[rt][3] = sQ[(row+8)*8 + 4 + t4];
        m2lo[rt] = sM2[row];
        m2hi[rt] = sM2[row+8];
    }
    float o[2][8][4];
    #pragma unroll
    for (int rt = 0; rt < 2; rt++)
        #pragma unroll
        for (int ct = 0; ct < 8; ct++)
            #pragma unroll
            for (int u = 0; u < 4; u++) o[rt][ct][u] = 0.f;
    float rs0[2] = {0.f, 0.f}, rs1[2] = {0.f, 0.f};

    for (int nt = 0; nt < 24; nt++){
        uint32 kb[2][2];
        #pragma unroll
        for (int h = 0; h < 2; h++){
            int key = nt*16 + h*8 + g4;
            kb[h][0] = sK[key*8 + t4];
            kb[h][1] = sK[key*8 + 4 + t4];
        }
        float sc2[2][2][4];
        #pragma unroll
        for (int rt = 0; rt < 2; rt++)
            #pragma unroll
            for (int h = 0; h < 2; h++){
                sc2[rt][h][0] = 0.f; sc2[rt][h][1] = 0.f;
                sc2[rt][h][2] = 0.f; sc2[rt][h][3] = 0.f;
                mma16816(sc2[rt][h], qf[rt], kb[h][0], kb[h][1]);
            }
        uint32 pf[2][4];
        #pragma unroll
        for (int rt = 0; rt < 2; rt++){
            #pragma unroll
            for (int h = 0; h < 2; h++){
                float e0 = ex2a(sc2[rt][h][0] - m2lo[rt]);
                float e1 = ex2a(sc2[rt][h][1] - m2lo[rt]);
                float e2 = ex2a(sc2[rt][h][2] - m2hi[rt]);
                float e3 = ex2a(sc2[rt][h][3] - m2hi[rt]);
                rs0[rt] += e0 + e1;
                rs1[rt] += e2 + e3;
                pf[rt][h*2]   = pkbf(e0, e1);
                pf[rt][h*2+1] = pkbf(e2, e3);
            }
        }
        // pf order must be {a0a1, a2a3, a4a5, a6a7} = {(r,k0),(r+8,k0),(r,k8),(r+8,k8)}
        // h=0 -> k in [0,8): pf[rt][0]=(r), pf[rt][1]=(r+8); h=1 -> pf[rt][2],(pf[rt][3]) ✓
        #pragma unroll
        for (int ct = 0; ct < 8; ct++){
            int ch = ct*8 + g4;
            uint32 vb0 = sVT[ch*204 + nt*8 + t4];
            uint32 vb1 = sVT[ch*204 + nt*8 + 4 + t4];
            mma16816(o[0][ct], pf[0], vb0, vb1);
            mma16816(o[1][ct], pf[1], vb0, vb1);
        }
    }

    // ---- epilogue ----
    #pragma unroll
    for (int rt = 0; rt < 2; rt++){
        float v0 = rs0[rt];
        v0 += __shfl_xor_sync(0xffffffffu, v0, 1);
        v0 += __shfl_xor_sync(0xffffffffu, v0, 2);
        float v1 = rs1[rt];
        v1 += __shfl_xor_sync(0xffffffffu, v1, 1);
        v1 += __shfl_xor_sync(0xffffffffu, v1, 2);
        float i0 = 1.f / v0, i1 = 1.f / v1;
        int row0 = rbase + rt*16 + g4, row1 = row0 + 8;
        int j0 = sJ[row0], j1 = sJ[row1];
        if (t4 == 0){
            g_bs[n][j0] = (sM2[row0] + lg2a(v0)) * LN2;
            g_bs[n][j1] = (sM2[row1] + lg2a(v1)) * LN2;
        }
        unsigned short* r0p = &g_ret[n][j0][0];
        unsigned short* r1p = &g_ret[n][j1][0];
        #pragma unroll
        for (int ct = 0; ct < 8; ct++){
            int ch = ct*8 + 2*t4;
            *(uint32*)&r0p[ch] = pkbf(o[rt][ct][0]*i0, o[rt][ct][1]*i0);
            *(uint32*)&r1p[ch] = pkbf(o[rt][ct][2]*i1, o[rt][ct][3]*i1);
        }
    }
}

// ---------------- K4: combine + residual + hist re-zero ----------------
__global__ void k_combine(const float* __restrict__ x, float* __restrict__ out){
    int gt = blockIdx.x * 256 + threadIdx.x;
    int n = gt >> 14, l = gt & (LSEQ - 1);
    float b0 = g_bs[n][l];
    float b1 = g_bs[n][LSEQ + l];
    float b2 = g_bs[n][2*LSEQ + l];
    float b3 = g_bs[n][3*LSEQ + l];
    float mx = fmaxf(fmaxf(b0, b1), fmaxf(b2, b3));
    float e0 = ex2a((b0 - mx)*LOG2E), e1 = ex2a((b1 - mx)*LOG2E);
    float e2 = ex2a((b2 - mx)*LOG2E), e3 = ex2a((b3 - mx)*LOG2E);
    float inv = 1.f / (e0 + e1 + e2 + e3);
    float p0 = e0*inv, p1 = e1*inv, p2 = e2*inv, p3 = e3*inv;

    const uint4* r0 = (const uint4*)&g_ret[n][l][0];
    const uint4* r1 = (const uint4*)&g_ret[n][LSEQ + l][0];
    const uint4* r2 = (const uint4*)&g_ret[n][2*LSEQ + l][0];
    const uint4* r3 = (const uint4*)&g_ret[n][3*LSEQ + l][0];
    const float4* x4 = (const float4*)&x[((size_t)n*LSEQ + l)*64];
    float4* o4 = (float4*)&out[((size_t)n*LSEQ + l)*64];
    #pragma unroll
    for (int t = 0; t < 8; t++){
        uint4 u0 = r0[t], u1 = r1[t], u2 = r2[t], u3 = r3[t];
        float4 xa = x4[2*t], xb = x4[2*t+1];
        float4 oa, ob;
        oa.x = xa.x + p0*blo(u0.x) + p1*blo(u1.x) + p2*blo(u2.x) + p3*blo(u3.x);
        oa.y = xa.y + p0*bhi(u0.x) + p1*bhi(u1.x) + p2*bhi(u2.x) + p3*bhi(u3.x);
        oa.z = xa.z + p0*blo(u0.y) + p1*blo(u1.y) + p2*blo(u2.y) + p3*blo(u3.y);
        oa.w = xa.w + p0*bhi(u0.y) + p1*bhi(u1.y) + p2*bhi(u2.y) + p3*bhi(u3.y);
        ob.x = xb.x + p0*blo(u0.z) + p1*blo(u1.z) + p2*blo(u2.z) + p3*blo(u3.z);
        ob.y = xb.y + p0*bhi(u0.z) + p1*bhi(u1.z) + p2*bhi(u2.z) + p3*bhi(u3.z);
        ob.z = xb.z + p0*blo(u0.w) + p1*blo(u1.w) + p2*blo(u2.w) + p3*blo(u3.w);
        ob.w = xb.w + p0*bhi(u0.w) + p1*bhi(u1.w) + p2*bhi(u2.w) + p3*bhi(u3.w);
        o4[2*t] = oa;
        o4[2*t+1] = ob;
    }
    int* hist = &g_tileHist[0][0][0];
    const int tot = NB*NTILE*NKEY;
    for (int idx = gt; idx < tot; idx += NB*LSEQ) hist[idx] = 0;
}

// ---------------- launch ----------------
extern "C" void kernel_launch(void* const* d_in, const int* in_sizes, int n_in,
                              void* d_out, int out_size){
    const float* x  = (const float*)d_in[0];
    const float* wm = (const float*)d_in[1];
    const float* wa = (const float*)d_in[2];
    const float* wb = (const float*)d_in[3];
    const float* rt = (const float*)d_in[4];
    float* out = (float*)d_out;

    static bool attr_done = false;
    if (!attr_done){
        cudaFuncSetAttribute(k_ehh, cudaFuncAttributeMaxDynamicSharedMemorySize, SMEM_EHH);
        cudaFuncSetAttribute(k_attn, cudaFuncAttributeMaxDynamicSharedMemorySize, SMEM_ATTN);
        attr_done = true;
    }

    k_ehh    <<<NB*(LSEQ/TL), 256, SMEM_EHH>>>(x, wm, wa, wb, rt);
    k_scan   <<<NB, 1024>>>();
    k_scatter<<<NB*NTILE, TILE>>>();
    k_attn   <<<NB*NH*KCH, 128, SMEM_ATTN>>>();
    k_combine<<<(NB*LSEQ)/256, 256>>>(x, out);
}